// round 14
// baseline (speedup 1.0000x reference)
#include <cuda_runtime.h>
#include <cuda_fp16.h>

#define T    4096
#define DIM  1024
#define HID  4096
#define E    8
#define KTOP 2
#define NROW (T * KTOP)

#define BM 128
#define BN 128
#define BK 64
#define MT 32            // max M-tiles per expert
#define NTHR 512         // 16 warps: 4 (m) x 4 (n), warp tile 32x32

// SMEM per stage: A[128][72h] (64 data + 8 pad), B[64][136h] (128 data + 8 pad)
#define PITCH_A  144             // bytes (36 words = 4 mod 32 -> conflict-free)
#define PITCH_B  272             // bytes (68 words = 4 mod 32 -> conflict-free)
#define PL_A     (128 * PITCH_A) // 18432
#define PL_B     (64 * PITCH_B)  // 17408
#define OFF_A    0
#define OFF_B    PL_A
#define STAGE_B  (PL_A + PL_B)           // 35840
#define GEMM_SMEM (1024 + 2 * STAGE_B)   // 72704

// ---------------- static scratch (96 MB total: proven safe) ------------------
__device__ int   g_counts[E];
__device__ int   g_fill[E];
__device__ int   g_offsets[E + 1];
__device__ int   g_topk_e[T * KTOP];
__device__ float g_topk_p[T * KTOP];
__device__ int   g_row_token[NROW];
__device__ int   g_tok_row[T * KTOP];

__device__ __half g_H[(size_t)NROW * HID];     // 64 MB
__device__ float  g_Hout[(size_t)NROW * DIM];  // 32 MB

// ---------------- PTX helpers ------------------------------------------------
__device__ __forceinline__ unsigned smem_u32(const void* p) {
    unsigned a;
    asm("{ .reg .u64 t; cvta.to.shared.u64 t, %1; cvt.u32.u64 %0, t; }" : "=r"(a) : "l"(p));
    return a;
}
__device__ __forceinline__ void ldsm4(unsigned* r, unsigned addr) {
    asm volatile("ldmatrix.sync.aligned.m8n8.x4.shared.b16 {%0,%1,%2,%3}, [%4];"
                 : "=r"(r[0]), "=r"(r[1]), "=r"(r[2]), "=r"(r[3]) : "r"(addr));
}
__device__ __forceinline__ void ldsm4t(unsigned* r, unsigned addr) {
    asm volatile("ldmatrix.sync.aligned.m8n8.x4.trans.shared.b16 {%0,%1,%2,%3}, [%4];"
                 : "=r"(r[0]), "=r"(r[1]), "=r"(r[2]), "=r"(r[3]) : "r"(addr));
}
__device__ __forceinline__ void mma16816(float* c, const unsigned* a, const unsigned* b) {
    asm volatile(
        "mma.sync.aligned.m16n8k16.row.col.f32.f16.f16.f32 "
        "{%0,%1,%2,%3}, {%4,%5,%6,%7}, {%8,%9}, {%0,%1,%2,%3};"
        : "+f"(c[0]), "+f"(c[1]), "+f"(c[2]), "+f"(c[3])
        : "r"(a[0]), "r"(a[1]), "r"(a[2]), "r"(a[3]), "r"(b[0]), "r"(b[1]));
}
__device__ __forceinline__ unsigned pack2h(float a, float b) {
    __half2 H = __halves2half2(__float2half_rn(a), __float2half_rn(b));
    return *(unsigned*)&H;
}

// ---------------- init -------------------------------------------------------
__global__ void init_kernel() {
    int i = threadIdx.x;
    if (i < E) { g_counts[i] = 0; g_fill[i] = 0; }
}

// ---------------- gating (exact fp32; one warp per token) --------------------
__global__ void gating_kernel(const float* __restrict__ x,
                              const float* __restrict__ gw,
                              const float* __restrict__ gb) {
    int warp = (blockIdx.x * blockDim.x + threadIdx.x) >> 5;
    int lane = threadIdx.x & 31;
    if (warp >= T) return;
    const float* xr = x + (size_t)warp * DIM;

    float acc[E];
#pragma unroll
    for (int e = 0; e < E; e++) acc[e] = 0.f;
    for (int d = lane; d < DIM; d += 32) {
        float xv = xr[d];
        float4 g0 = *(const float4*)(gw + d * E);
        float4 g1 = *(const float4*)(gw + d * E + 4);
        acc[0] += xv * g0.x; acc[1] += xv * g0.y;
        acc[2] += xv * g0.z; acc[3] += xv * g0.w;
        acc[4] += xv * g1.x; acc[5] += xv * g1.y;
        acc[6] += xv * g1.z; acc[7] += xv * g1.w;
    }
#pragma unroll
    for (int e = 0; e < E; e++)
#pragma unroll
        for (int off = 16; off > 0; off >>= 1)
            acc[e] += __shfl_down_sync(0xffffffffu, acc[e], off);

    if (lane == 0) {
        float lg[E];
        float m = -1e30f;
#pragma unroll
        for (int e = 0; e < E; e++) { lg[e] = acc[e] + gb[e]; m = fmaxf(m, lg[e]); }
        float s = 0.f;
#pragma unroll
        for (int e = 0; e < E; e++) { lg[e] = expf(lg[e] - m); s += lg[e]; }
        int e1 = 0;
#pragma unroll
        for (int e = 1; e < E; e++) if (lg[e] > lg[e1]) e1 = e;
        int e2 = (e1 == 0) ? 1 : 0;
#pragma unroll
        for (int e = 0; e < E; e++) if (e != e1 && e != e2 && lg[e] > lg[e2]) e2 = e;
        float inv = 1.0f / s;
        g_topk_e[warp * 2 + 0] = e1;
        g_topk_e[warp * 2 + 1] = e2;
        g_topk_p[warp * 2 + 0] = lg[e1] * inv;
        g_topk_p[warp * 2 + 1] = lg[e2] * inv;
        atomicAdd(&g_counts[e1], 1);
        atomicAdd(&g_counts[e2], 1);
    }
}

__global__ void scan_kernel() {
    if (threadIdx.x == 0) {
        int acc = 0;
        g_offsets[0] = 0;
        for (int e = 0; e < E; e++) { acc += g_counts[e]; g_offsets[e + 1] = acc; }
    }
}

__global__ void assign_kernel() {
    int t = blockIdx.x * blockDim.x + threadIdx.x;
    if (t >= T) return;
#pragma unroll
    for (int k = 0; k < KTOP; k++) {
        int e = g_topk_e[t * 2 + k];
        int slot = atomicAdd(&g_fill[e], 1);
        int row = g_offsets[e] + slot;
        g_row_token[row] = t;
        g_tok_row[t * 2 + k] = row;
    }
}

// ---------------- grouped HMMA GEMM (fp16 x fp16, fp32 acc), BK=64 -----------
// R11 skeleton (ldg at loop top, sts at loop bottom, one sync per stage);
// ONLY change vs R11: BK 32 -> 64 (halves stage count / sync overhead).
// G1: C[rows,HID] = gather(x)@w1, +b1, ReLU -> g_H (fp16)
// G2: C[rows,DIM] = H @ w2 -> g_Hout (fp32)
template <int KD, int NTOT, bool G1>
__global__ void __launch_bounds__(NTHR, 1)
moe_gemm(const float* __restrict__ xA,
         const float* __restrict__ wB,    // [E][KD][NTOT] fp32 (k-major rows)
         const float* __restrict__ bias) {
    int e  = blockIdx.y >> 5;
    int mt = blockIdx.y & 31;
    int cnt = g_counts[e];
    int m0 = mt * BM;
    if (m0 >= cnt) return;
    int n0 = blockIdx.x * BN;
    int base = g_offsets[e];

    extern __shared__ char smem[];
    int* toks = (int*)smem;
    char* tiles = smem + 1024;

    int tid  = threadIdx.x;
    int lane = tid & 31;
    int wid  = tid >> 5;

    if (G1 && tid < BM) {
        int m = m0 + tid;
        toks[tid] = g_row_token[base + (m < cnt ? m : cnt - 1)];
    }
    __syncthreads();

    // ---- load mapping: A: 4 threads/row, 16 elts each; B: 8 threads/k-row, 16 cols each
    int arow = tid >> 2, kh = (tid & 3) * 16;
    int brow = tid >> 3, nh = (tid & 7) * 16;

    const float* aF = nullptr;
    const __half* aH = nullptr;
    if (G1) {
        aF = xA + (size_t)toks[arow] * KD + kh;
    } else {
        int m = m0 + arow; if (m >= cnt) m = cnt - 1;
        aH = g_H + (size_t)(base + m) * KD + kh;
    }
    const float* bF = wB + ((size_t)e * KD + brow) * NTOT + n0 + nh;

    unsigned aoff = (unsigned)(arow * PITCH_A + kh * 2);
    unsigned boff = (unsigned)(brow * PITCH_B + nh * 2);

    // ---- staged registers: 16 A floats (or 16 halves) + 16 B floats
    float fa[16];
    uint4 ha[2];
    float fb[16];

    auto ldg_stage = [&](int c) {
        int kk = c * BK;
        if (G1) {
#pragma unroll
            for (int q = 0; q < 4; q++)
                *(float4*)(fa + 4 * q) = __ldg((const float4*)(aF + kk + 4 * q));
        } else {
            ha[0] = __ldg((const uint4*)(aH + kk));
            ha[1] = __ldg((const uint4*)(aH + kk + 8));
        }
        const float* bp = bF + (size_t)kk * NTOT;
#pragma unroll
        for (int q = 0; q < 4; q++)
            *(float4*)(fb + 4 * q) = __ldg((const float4*)(bp + 4 * q));
    };

    auto sts_stage = [&](int st) {
        char* stb = tiles + st * STAGE_B;
        if (G1) {
            unsigned hh[8];
#pragma unroll
            for (int q = 0; q < 8; q++) hh[q] = pack2h(fa[2 * q], fa[2 * q + 1]);
            *(uint4*)(stb + OFF_A + aoff)      = make_uint4(hh[0], hh[1], hh[2], hh[3]);
            *(uint4*)(stb + OFF_A + aoff + 16) = make_uint4(hh[4], hh[5], hh[6], hh[7]);
        } else {
            *(uint4*)(stb + OFF_A + aoff)      = ha[0];
            *(uint4*)(stb + OFF_A + aoff + 16) = ha[1];
        }
        unsigned hh[8];
#pragma unroll
        for (int q = 0; q < 8; q++) hh[q] = pack2h(fb[2 * q], fb[2 * q + 1]);
        *(uint4*)(stb + OFF_B + boff)      = make_uint4(hh[0], hh[1], hh[2], hh[3]);
        *(uint4*)(stb + OFF_B + boff + 16) = make_uint4(hh[4], hh[5], hh[6], hh[7]);
    };

    // ---- compute mapping: warp (wm, wn) owns 32x32
    int wm = wid >> 2;     // 0..3
    int wn = wid & 3;      // 0..3
    unsigned sbase = smem_u32(tiles);
    unsigned a_off = (unsigned)((wm * 32 + (lane & 15)) * PITCH_A + (lane >> 4) * 16);
    unsigned b_off = (unsigned)((lane & 15) * PITCH_B + (wn * 32 + (lane >> 4) * 8) * 2);

    float acc[2][4][4];
#pragma unroll
    for (int i = 0; i < 2; i++)
#pragma unroll
        for (int j = 0; j < 4; j++)
#pragma unroll
            for (int q = 0; q < 4; q++) acc[i][j][q] = 0.f;

    auto compute_stage = [&](int st) {
        unsigned stb = sbase + st * STAGE_B;
#pragma unroll
        for (int ks = 0; ks < 4; ks++) {
            unsigned afr[2][4], bfr[4][2];
#pragma unroll
            for (int i = 0; i < 2; i++) {
                unsigned ad = stb + a_off + (unsigned)(i * 16 * PITCH_A) + (unsigned)(ks * 32);
                ldsm4(afr[i], ad + OFF_A);
            }
#pragma unroll
            for (int jj = 0; jj < 2; jj++) {
                unsigned bd = stb + b_off + (unsigned)(ks * 16 * PITCH_B) + (unsigned)(jj * 32);
                unsigned th[4];
                ldsm4t(th, bd + OFF_B);
                bfr[2 * jj][0] = th[0]; bfr[2 * jj][1] = th[1];
                bfr[2 * jj + 1][0] = th[2]; bfr[2 * jj + 1][1] = th[3];
            }
#pragma unroll
            for (int i = 0; i < 2; i++)
#pragma unroll
                for (int j = 0; j < 4; j++)
                    mma16816(acc[i][j], afr[i], bfr[j]);
        }
    };

    const int NC = KD / BK;
    ldg_stage(0);
    sts_stage(0);
    __syncthreads();
    for (int c = 0; c < NC; c++) {
        if (c + 1 < NC) ldg_stage(c + 1);
        compute_stage(c & 1);
        if (c + 1 < NC) sts_stage((c + 1) & 1);
        __syncthreads();
    }

    // ---- epilogue
    int r_base = wm * 32 + (lane >> 2);
    int c_base = n0 + wn * 32 + 2 * (lane & 3);
#pragma unroll
    for (int i = 0; i < 2; i++) {
#pragma unroll
        for (int h = 0; h < 2; h++) {
            int m = m0 + r_base + i * 16 + h * 8;
            if (m >= cnt) continue;
            size_t orow = (size_t)(base + m);
#pragma unroll
            for (int j = 0; j < 4; j++) {
                int n = c_base + j * 8;
                float v0 = acc[i][j][h * 2];
                float v1 = acc[i][j][h * 2 + 1];
                if (G1) {
                    v0 += __ldg(&bias[(size_t)e * NTOT + n]);
                    v1 += __ldg(&bias[(size_t)e * NTOT + n + 1]);
                    v0 = fmaxf(v0, 0.f); v1 = fmaxf(v1, 0.f);
                    *(unsigned*)(g_H + orow * HID + n) = pack2h(v0, v1);
                } else {
                    float2 v; v.x = v0; v.y = v1;
                    *(float2*)(g_Hout + orow * DIM + n) = v;
                }
            }
        }
    }
}

// ---------------- combine ----------------------------------------------------
__global__ void combine_kernel(const float* __restrict__ b2,
                               float* __restrict__ out) {
    int t = blockIdx.x;
    int e1 = g_topk_e[t * 2 + 0], e2 = g_topk_e[t * 2 + 1];
    float p1 = g_topk_p[t * 2 + 0], p2 = g_topk_p[t * 2 + 1];
    int r1 = g_tok_row[t * 2 + 0], r2 = g_tok_row[t * 2 + 1];
    const float* h1 = g_Hout + (size_t)r1 * DIM;
    const float* h2 = g_Hout + (size_t)r2 * DIM;
    const float* bb1 = b2 + (size_t)e1 * DIM;
    const float* bb2 = b2 + (size_t)e2 * DIM;
    for (int d = threadIdx.x; d < DIM; d += blockDim.x) {
        out[(size_t)t * DIM + d] = p1 * (h1[d] + bb1[d]) + p2 * (h2[d] + bb2[d]);
    }
}

// ---------------- launch -----------------------------------------------------
extern "C" void kernel_launch(void* const* d_in, const int* in_sizes, int n_in,
                              void* d_out, int out_size) {
    (void)in_sizes; (void)n_in; (void)out_size;
    const float* x  = (const float*)d_in[0];
    const float* gw = (const float*)d_in[1];
    const float* gb = (const float*)d_in[2];
    const float* w1 = (const float*)d_in[3];
    const float* b1 = (const float*)d_in[4];
    const float* w2 = (const float*)d_in[5];
    const float* b2 = (const float*)d_in[6];
    float* out = (float*)d_out;

    cudaFuncSetAttribute((const void*)moe_gemm<DIM, HID, true>,
                         cudaFuncAttributeMaxDynamicSharedMemorySize, GEMM_SMEM);
    cudaFuncSetAttribute((const void*)moe_gemm<HID, DIM, false>,
                         cudaFuncAttributeMaxDynamicSharedMemorySize, GEMM_SMEM);

    init_kernel<<<1, 32>>>();
    gating_kernel<<<T / 8, 256>>>(x, gw, gb);
    scan_kernel<<<1, 32>>>();
    assign_kernel<<<T / 256, 256>>>();

    moe_gemm<DIM, HID, true><<<dim3(HID / BN, E * MT), NTHR, GEMM_SMEM>>>(x, w1, b1);
    moe_gemm<HID, DIM, false><<<dim3(DIM / BN, E * MT), NTHR, GEMM_SMEM>>>(x, w2, b2);

    combine_kernel<<<T, 256>>>(b2, out);
}

// round 17
// speedup vs baseline: 1.1959x; 1.1959x over previous
#include <cuda_runtime.h>
#include <cuda_fp16.h>

#define T    4096
#define DIM  1024
#define HID  4096
#define E    8
#define KTOP 2
#define NROW (T * KTOP)

#define BM 128
#define BN 128
#define BK 32
#define MT 32            // max M-tiles per expert
#define NTHR 512         // 16 warps: 4 (m) x 4 (n), warp tile 32x32

// SMEM regions:
//  [0,1024)            toks
//  AREG: 3 stages x A[128][40h] pitch 80B      (fp16 compute layout)
//  BREG: 2 stages x B[32][136h] pitch 272B     (fp16 compute layout)
//  STG:  3 stages x Braw[32][132f] pitch 528B  (fp32 staging for cp.async)
#define PITCH_A  80
#define PITCH_B  272
#define PITCH_S  528
#define PL_A     (128 * PITCH_A)   // 10240
#define PL_B     (32 * PITCH_B)    // 8704
#define PL_S     (32 * PITCH_S)    // 16896
#define SOFF_A   1024
#define SOFF_B   (SOFF_A + 3 * PL_A)           // 31744
#define SOFF_S   (SOFF_B + 2 * PL_B)           // 49152
#define GEMM_SMEM (SOFF_S + 3 * PL_S)          // 99840

// ---------------- static scratch (64.1 MB: R13-proven envelope) --------------
__device__ int   g_counts[E];
__device__ int   g_fill[E];
__device__ int   g_offsets[E + 1];
__device__ int   g_topk_e[T * KTOP];
__device__ float g_topk_p[T * KTOP];
__device__ int   g_row_token[NROW];
__device__ float g_row_p[NROW];

__device__ __half g_H[(size_t)NROW * HID];     // 64 MB

// ---------------- PTX helpers ------------------------------------------------
__device__ __forceinline__ unsigned smem_u32(const void* p) {
    unsigned a;
    asm("{ .reg .u64 t; cvta.to.shared.u64 t, %1; cvt.u32.u64 %0, t; }" : "=r"(a) : "l"(p));
    return a;
}
#define CPA16(sa, ga) \
    asm volatile("cp.async.cg.shared.global [%0], [%1], 16;" :: "r"(sa), "l"(ga) : "memory")
#define CP_COMMIT() asm volatile("cp.async.commit_group;" ::: "memory")
#define CP_WAIT1()  asm volatile("cp.async.wait_group 1;" ::: "memory")

__device__ __forceinline__ void ldsm4(unsigned* r, unsigned addr) {
    asm volatile("ldmatrix.sync.aligned.m8n8.x4.shared.b16 {%0,%1,%2,%3}, [%4];"
                 : "=r"(r[0]), "=r"(r[1]), "=r"(r[2]), "=r"(r[3]) : "r"(addr));
}
__device__ __forceinline__ void ldsm4t(unsigned* r, unsigned addr) {
    asm volatile("ldmatrix.sync.aligned.m8n8.x4.trans.shared.b16 {%0,%1,%2,%3}, [%4];"
                 : "=r"(r[0]), "=r"(r[1]), "=r"(r[2]), "=r"(r[3]) : "r"(addr));
}
__device__ __forceinline__ void mma16816(float* c, const unsigned* a, const unsigned* b) {
    asm volatile(
        "mma.sync.aligned.m16n8k16.row.col.f32.f16.f16.f32 "
        "{%0,%1,%2,%3}, {%4,%5,%6,%7}, {%8,%9}, {%0,%1,%2,%3};"
        : "+f"(c[0]), "+f"(c[1]), "+f"(c[2]), "+f"(c[3])
        : "r"(a[0]), "r"(a[1]), "r"(a[2]), "r"(a[3]), "r"(b[0]), "r"(b[1]));
}
__device__ __forceinline__ unsigned pack2h(float a, float b) {
    __half2 H = __halves2half2(__float2half_rn(a), __float2half_rn(b));
    return *(unsigned*)&H;
}

// ---------------- init / zero ------------------------------------------------
__global__ void init_kernel() {
    int i = threadIdx.x;
    if (i < E) { g_counts[i] = 0; g_fill[i] = 0; }
}
__global__ void zero_out_kernel(float* __restrict__ out) {
    size_t i = ((size_t)blockIdx.x * blockDim.x + threadIdx.x) * 4;
    float4 z; z.x = 0.f; z.y = 0.f; z.z = 0.f; z.w = 0.f;
    *(float4*)(out + i) = z;
}

// ---------------- gating (exact fp32; one warp per token) --------------------
__global__ void gating_kernel(const float* __restrict__ x,
                              const float* __restrict__ gw,
                              const float* __restrict__ gb) {
    int warp = (blockIdx.x * blockDim.x + threadIdx.x) >> 5;
    int lane = threadIdx.x & 31;
    if (warp >= T) return;
    const float* xr = x + (size_t)warp * DIM;

    float acc[E];
#pragma unroll
    for (int e = 0; e < E; e++) acc[e] = 0.f;
    for (int d = lane; d < DIM; d += 32) {
        float xv = xr[d];
        float4 g0 = *(const float4*)(gw + d * E);
        float4 g1 = *(const float4*)(gw + d * E + 4);
        acc[0] += xv * g0.x; acc[1] += xv * g0.y;
        acc[2] += xv * g0.z; acc[3] += xv * g0.w;
        acc[4] += xv * g1.x; acc[5] += xv * g1.y;
        acc[6] += xv * g1.z; acc[7] += xv * g1.w;
    }
#pragma unroll
    for (int e = 0; e < E; e++)
#pragma unroll
        for (int off = 16; off > 0; off >>= 1)
            acc[e] += __shfl_down_sync(0xffffffffu, acc[e], off);

    if (lane == 0) {
        float lg[E];
        float m = -1e30f;
#pragma unroll
        for (int e = 0; e < E; e++) { lg[e] = acc[e] + gb[e]; m = fmaxf(m, lg[e]); }
        float s = 0.f;
#pragma unroll
        for (int e = 0; e < E; e++) { lg[e] = expf(lg[e] - m); s += lg[e]; }
        int e1 = 0;
#pragma unroll
        for (int e = 1; e < E; e++) if (lg[e] > lg[e1]) e1 = e;
        int e2 = (e1 == 0) ? 1 : 0;
#pragma unroll
        for (int e = 0; e < E; e++) if (e != e1 && e != e2 && lg[e] > lg[e2]) e2 = e;
        float inv = 1.0f / s;
        g_topk_e[warp * 2 + 0] = e1;
        g_topk_e[warp * 2 + 1] = e2;
        g_topk_p[warp * 2 + 0] = lg[e1] * inv;
        g_topk_p[warp * 2 + 1] = lg[e2] * inv;
        atomicAdd(&g_counts[e1], 1);
        atomicAdd(&g_counts[e2], 1);
    }
}

__global__ void scan_kernel() {
    if (threadIdx.x == 0) {
        int acc = 0;
        g_offsets[0] = 0;
        for (int e = 0; e < E; e++) { acc += g_counts[e]; g_offsets[e + 1] = acc; }
    }
}

__global__ void assign_kernel() {
    int t = blockIdx.x * blockDim.x + threadIdx.x;
    if (t >= T) return;
#pragma unroll
    for (int k = 0; k < KTOP; k++) {
        int e = g_topk_e[t * 2 + k];
        int slot = atomicAdd(&g_fill[e], 1);
        int row = g_offsets[e] + slot;
        g_row_token[row] = t;
        g_row_p[row] = g_topk_p[t * 2 + k];
    }
}

// ---------------- grouped HMMA GEMM, cp.async staged + smem convert ----------
// B (weights, fp32) stream via cp.async into STG ring, converted in-smem to
// fp16 BREG. A: G1 = gathered x via register path (L2-hot); G2 = g_H fp16 via
// direct cp.async into AREG. One group per iter; wait_group 1 + sync before
// convert guarantees cross-thread cp.async completion.
// G1: g_H = relu(gather(x) @ w1 + b1)       (fp16 out)
// G2: out[tok] += p * (g_H @ w2 + b2)       (atomicAdd, 2 addends -> determ.)
template <int KD, int NTOT, bool G1>
__global__ void __launch_bounds__(NTHR, 1)
moe_gemm(const float* __restrict__ xA,      // G1 only
         const float* __restrict__ wB,      // [E][KD][NTOT] fp32 k-major
         const float* __restrict__ bias,
         float* __restrict__ outp) {
    int e  = blockIdx.y >> 5;
    int mt = blockIdx.y & 31;
    int cnt = g_counts[e];
    int m0 = mt * BM;
    if (m0 >= cnt) return;
    int n0 = blockIdx.x * BN;
    int base = g_offsets[e];

    extern __shared__ char smem[];
    int* toks = (int*)smem;
    unsigned sbase = smem_u32(smem);

    int tid  = threadIdx.x;
    int lane = tid & 31;
    int wid  = tid >> 5;

    if (G1 && tid < BM) {
        int m = m0 + tid;
        toks[tid] = g_row_token[base + (m < cnt ? m : cnt - 1)];
    }
    __syncthreads();

    // ---- B staging cp.async mapping: 2 chunks/thread (rows r, r+16)
    int brow0 = tid >> 5;            // 0..15
    int brow1 = brow0 + 16;          // 16..31
    int bseg  = tid & 31;            // 16B segment (4 fp32)
    const float* bR0 = wB + ((size_t)e * KD + brow0) * NTOT + n0 + bseg * 4;
    const float* bR1 = wB + ((size_t)e * KD + brow1) * NTOT + n0 + bseg * 4;
    unsigned sg0 = sbase + (unsigned)(SOFF_S + brow0 * PITCH_S + bseg * 16);
    unsigned sg1 = sbase + (unsigned)(SOFF_S + brow1 * PITCH_S + bseg * 16);

    // ---- A mapping
    int arow = tid >> 2, aseg = tid & 3;
    const float* aFx = nullptr;       // G1
    const __half* aHh = nullptr;      // G2
    if (G1) {
        aFx = xA + (size_t)toks[arow] * KD + aseg * 8;
    } else {
        int m = m0 + arow; if (m >= cnt) m = cnt - 1;
        aHh = g_H + (size_t)(base + m) * KD + aseg * 8;
    }
    unsigned adst = sbase + (unsigned)(SOFF_A + arow * PITCH_A + aseg * 16);

    auto load_stage = [&](int c) {
        int kk = c * BK;
        unsigned so = (unsigned)((c % 3) * PL_S);
        CPA16(sg0 + so, bR0 + (size_t)kk * NTOT);
        CPA16(sg1 + so, bR1 + (size_t)kk * NTOT);
        if (!G1) CPA16(adst + (unsigned)((c % 3) * PL_A), aHh + kk);
    };

    // ---- G1 A register path
    float fa[8];
    auto ldg_x = [&](int c) {
        *(float4*)(fa)     = *(const float4*)(aFx + c * BK);
        *(float4*)(fa + 4) = *(const float4*)(aFx + c * BK + 4);
    };
    auto sts_A = [&](int c) {
        uint4 o;
        o.x = pack2h(fa[0], fa[1]); o.y = pack2h(fa[2], fa[3]);
        o.z = pack2h(fa[4], fa[5]); o.w = pack2h(fa[6], fa[7]);
        *(uint4*)(smem + SOFF_A + (c % 3) * PL_A + arow * PITCH_A + aseg * 16) = o;
    };

    // ---- B convert: 8 fp32/thread, STG -> BREG
    int crow = tid >> 4;             // 0..31
    int ccol = (tid & 15) * 8;       // 0..120
    auto convert_B = [&](int c) {
        const char* src = smem + SOFF_S + (c % 3) * PL_S + crow * PITCH_S + ccol * 4;
        float4 u0 = *(const float4*)(src);
        float4 u1 = *(const float4*)(src + 16);
        uint4 o;
        o.x = pack2h(u0.x, u0.y); o.y = pack2h(u0.z, u0.w);
        o.z = pack2h(u1.x, u1.y); o.w = pack2h(u1.z, u1.w);
        *(uint4*)(smem + SOFF_B + (c & 1) * PL_B + crow * PITCH_B + ccol * 2) = o;
    };

    // ---- compute mapping: warp (wm, wn) owns 32x32
    int wm = wid >> 2;
    int wn = wid & 3;
    unsigned a_off = sbase + (unsigned)(SOFF_A + (wm * 32 + (lane & 15)) * PITCH_A + (lane >> 4) * 16);
    unsigned b_off = sbase + (unsigned)(SOFF_B + (lane & 15) * PITCH_B + (wn * 32 + (lane >> 4) * 8) * 2);

    float acc[2][4][4];
#pragma unroll
    for (int i = 0; i < 2; i++)
#pragma unroll
        for (int j = 0; j < 4; j++)
#pragma unroll
            for (int q = 0; q < 4; q++) acc[i][j][q] = 0.f;

    auto compute_stage = [&](int c) {
        unsigned ao = (unsigned)((c % 3) * PL_A);
        unsigned bo = (unsigned)((c & 1) * PL_B);
#pragma unroll
        for (int ks = 0; ks < 2; ks++) {
            unsigned afr[2][4], bfr[4][2];
#pragma unroll
            for (int i = 0; i < 2; i++)
                ldsm4(afr[i], a_off + ao + (unsigned)(i * 16 * PITCH_A) + (unsigned)(ks * 32));
#pragma unroll
            for (int jj = 0; jj < 2; jj++) {
                unsigned th[4];
                ldsm4t(th, b_off + bo + (unsigned)(ks * 16 * PITCH_B) + (unsigned)(jj * 32));
                bfr[2 * jj][0] = th[0]; bfr[2 * jj][1] = th[1];
                bfr[2 * jj + 1][0] = th[2]; bfr[2 * jj + 1][1] = th[3];
            }
#pragma unroll
            for (int i = 0; i < 2; i++)
#pragma unroll
                for (int j = 0; j < 4; j++)
                    mma16816(acc[i][j], afr[i], bfr[j]);
        }
    };

    const int NC = KD / BK;
    // prologue: stages 0,1 in flight; stage 0 converted and visible
    load_stage(0); CP_COMMIT();
    load_stage(1); CP_COMMIT();
    if (G1) ldg_x(0);
    CP_WAIT1();          // group 0 complete (own), then barrier -> all threads'
    __syncthreads();
    convert_B(0);
    if (G1) { sts_A(0); ldg_x(1); }
    __syncthreads();

    for (int c = 0; c < NC; c++) {
        if (c + 2 < NC) load_stage(c + 2);
        CP_COMMIT();                  // constant group accounting
        compute_stage(c);
        CP_WAIT1();                   // group (c+1) complete for this thread
        __syncthreads();              // ... and for all threads
        if (c + 1 < NC) {
            convert_B(c + 1);
            if (G1) { sts_A(c + 1); if (c + 2 < NC) ldg_x(c + 2); }
        }
        __syncthreads();              // converted stage visible for next iter
    }

    // ---- epilogue
    int r_base = wm * 32 + (lane >> 2);
    int c_base = n0 + wn * 32 + 2 * (lane & 3);
#pragma unroll
    for (int i = 0; i < 2; i++) {
#pragma unroll
        for (int h = 0; h < 2; h++) {
            int m = m0 + r_base + i * 16 + h * 8;
            if (m >= cnt) continue;
            size_t orow = (size_t)(base + m);
            int tok = 0; float p = 0.f;
            if (!G1) { tok = g_row_token[orow]; p = g_row_p[orow]; }
#pragma unroll
            for (int j = 0; j < 4; j++) {
                int n = c_base + j * 8;
                float v0 = acc[i][j][h * 2];
                float v1 = acc[i][j][h * 2 + 1];
                if (G1) {
                    v0 += __ldg(&bias[(size_t)e * NTOT + n]);
                    v1 += __ldg(&bias[(size_t)e * NTOT + n + 1]);
                    v0 = fmaxf(v0, 0.f); v1 = fmaxf(v1, 0.f);
                    *(unsigned*)(g_H + orow * HID + n) = pack2h(v0, v1);
                } else {
                    v0 = p * (v0 + __ldg(&bias[(size_t)e * NTOT + n]));
                    v1 = p * (v1 + __ldg(&bias[(size_t)e * NTOT + n + 1]));
                    atomicAdd(outp + (size_t)tok * DIM + n, v0);
                    atomicAdd(outp + (size_t)tok * DIM + n + 1, v1);
                }
            }
        }
    }
}

// ---------------- launch -----------------------------------------------------
extern "C" void kernel_launch(void* const* d_in, const int* in_sizes, int n_in,
                              void* d_out, int out_size) {
    (void)in_sizes; (void)n_in; (void)out_size;
    const float* x  = (const float*)d_in[0];
    const float* gw = (const float*)d_in[1];
    const float* gb = (const float*)d_in[2];
    const float* w1 = (const float*)d_in[3];
    const float* b1 = (const float*)d_in[4];
    const float* w2 = (const float*)d_in[5];
    const float* b2 = (const float*)d_in[6];
    float* out = (float*)d_out;

    cudaFuncSetAttribute((const void*)moe_gemm<DIM, HID, true>,
                         cudaFuncAttributeMaxDynamicSharedMemorySize, GEMM_SMEM);
    cudaFuncSetAttribute((const void*)moe_gemm<HID, DIM, false>,
                         cudaFuncAttributeMaxDynamicSharedMemorySize, GEMM_SMEM);

    init_kernel<<<1, 32>>>();
    gating_kernel<<<T / 8, 256>>>(x, gw, gb);
    scan_kernel<<<1, 32>>>();
    assign_kernel<<<T / 256, 256>>>();
    zero_out_kernel<<<(T * DIM) / (256 * 4), 256>>>(out);

    moe_gemm<DIM, HID, true><<<dim3(HID / BN, E * MT), NTHR, GEMM_SMEM>>>(x, w1, b1, nullptr);
    moe_gemm<HID, DIM, false><<<dim3(DIM / BN, E * MT), NTHR, GEMM_SMEM>>>(x, w2, b2, out);
}